// round 10
// baseline (speedup 1.0000x reference)
#include <cuda_runtime.h>
#include <cstdint>

#define Bdim 2
#define Hdim 16
#define Sdim 2048
#define Ddim 128
#define QT 128            // q-tile rows per CTA
#define PH_KV 64          // kv rows per phase (32 per group)
#define NPH (Sdim / PH_KV)   // 32 phases
#define NTHREADS 512
#define WST 68            // fp16 tile word stride (ldmatrix conflict-free)

// smem word offsets
#define QS_OFF  0
#define K16_OFF (QT * WST)                    // 8704
#define V16_OFF (K16_OFF + 4 * 32 * WST)      // K16: 2grp x 2buf x 32 rows
#define KF_OFF  (V16_OFF + 4 * 32 * WST)      // V16: same
#define VF_OFF  (KF_OFF + 2 * 32 * 128)       // fp32 staging: 2grp x 32 x 128
#define SMEM_WORDS (VF_OFF + 2 * 32 * 128)
#define SMEM_BYTES (SMEM_WORDS * 4)           // 169984 B -> 1 CTA/SM

// ---------------------------------------------------------------------------
static __device__ __forceinline__ uint32_t h2(float lo, float hi) {
    uint32_t r;
    asm("cvt.rn.f16x2.f32 %0, %1, %2;" : "=r"(r) : "f"(hi), "f"(lo));
    return r;
}
// relu^2 in f16x2
static __device__ __forceinline__ uint32_t hsq(uint32_t w) {
    uint32_t r;
    asm("max.f16x2 %0, %1, %2;" : "=r"(r) : "r"(w), "r"(0u));
    asm("mul.f16x2 %0, %1, %1;" : "=r"(r) : "r"(r));
    return r;
}

static __device__ __forceinline__ void mma16(float* d,
        uint32_t a0, uint32_t a1, uint32_t a2, uint32_t a3,
        uint32_t b0, uint32_t b1) {
    asm volatile(
        "mma.sync.aligned.m16n8k16.row.col.f32.f16.f16.f32 "
        "{%0,%1,%2,%3}, {%4,%5,%6,%7}, {%8,%9}, {%0,%1,%2,%3};"
        : "+f"(d[0]), "+f"(d[1]), "+f"(d[2]), "+f"(d[3])
        : "r"(a0), "r"(a1), "r"(a2), "r"(a3), "r"(b0), "r"(b1));
}

static __device__ __forceinline__ void ldm4(uint32_t addr, uint32_t* r) {
    asm volatile("ldmatrix.sync.aligned.m8n8.x4.shared.b16 {%0,%1,%2,%3}, [%4];"
        : "=r"(r[0]), "=r"(r[1]), "=r"(r[2]), "=r"(r[3]) : "r"(addr));
}
static __device__ __forceinline__ void ldm4t(uint32_t addr, uint32_t* r) {
    asm volatile("ldmatrix.sync.aligned.m8n8.x4.trans.shared.b16 {%0,%1,%2,%3}, [%4];"
        : "=r"(r[0]), "=r"(r[1]), "=r"(r[2]), "=r"(r[3]) : "r"(addr));
}

static __device__ __forceinline__ void cp16(const float* smem_dst, const float* gsrc) {
    unsigned sa = (unsigned)__cvta_generic_to_shared(smem_dst);
    asm volatile("cp.async.cg.shared.global [%0], [%1], 16;" :: "r"(sa), "l"(gsrc));
}
#define CP_COMMIT() asm volatile("cp.async.commit_group;" ::: "memory")
#define CP_WAIT0()  asm volatile("cp.async.wait_group 0;" ::: "memory")

static __device__ __forceinline__ void bar_sync(int id, int cnt) {
    asm volatile("bar.sync %0, %1;" :: "r"(id), "r"(cnt) : "memory");
}

// ---------------------------------------------------------------------------
// One CTA (512 thr, 16 warps) = one (b,h) x one 128-row q-tile. 1 CTA/SM,
// 4 warps/SMSP. wm = wid&7 (m16 block), wn = wid>>3 (kv group, 32 rows/phase).
// Per phase: issue cp.async (fp32 K/V, tile t+1) -> GEMM1 S(m16 x kv32)
// (ldmatrix frags) -> P = relu^2 f16x2 (C->A direct) -> GEMM2 O(m16 x d128)
// (ldmatrix.trans V) -> cp.wait + fp32->fp16 smem convert into spare buffer.
// One 256-wide named bar per phase per group. O reduced across groups at end.
// ---------------------------------------------------------------------------
__global__ void __launch_bounds__(NTHREADS, 1)
attn_relu2_kernel(const float* __restrict__ q, const float* __restrict__ k,
                  const float* __restrict__ v, const float* __restrict__ scale_p,
                  float* __restrict__ out) {
    extern __shared__ uint32_t smw[];
    uint32_t* QW = smw + QS_OFF;
    float* KF = reinterpret_cast<float*>(smw + KF_OFF);
    float* VF = reinterpret_cast<float*>(smw + VF_OFF);

    const int tid  = threadIdx.x;
    const int lane = tid & 31;
    const int g    = lane >> 2;
    const int t4   = lane & 3;
    const int wid  = tid >> 5;
    const int wm   = wid & 7;      // m16 block
    const int wn   = wid >> 3;     // kv group
    const int tid_g = tid & 255;   // thread id within group

    const int bh = blockIdx.x >> 4;
    const int q0 = (blockIdx.x & 15) << 7;

    const float* kbase = k + (size_t)bh * Sdim * Ddim;
    const float* vbase = v + (size_t)bh * Sdim * Ddim;

    // ldmatrix lane geometry
    const int rl8 = (((lane >> 3) & 1) << 3) + (lane & 7);  // row within 16
    const int c4  = ((lane >> 4) & 1) << 2;                 // 0 or 4 words

    const uint32_t sb = (uint32_t)__cvta_generic_to_shared(smw);
    const uint32_t qa0 = sb + 4 * (QS_OFF + (wm * 16 + rl8) * WST + c4);

    // group staging bases
    float* kf = KF + wn * 32 * 128;
    float* vf = VF + wn * 32 * 128;

    // ---- Q fill (scale folded, fp16, natural row-major) ----
    {
        const float scl = *scale_p;
        const float* qg = q + ((size_t)bh * Sdim + q0) * Ddim;
        #pragma unroll
        for (int i = 0; i < 8; i++) {
            int c = tid + NTHREADS * i;       // 0..4095
            int r = c >> 5, j = c & 31;
            float4 f = *reinterpret_cast<const float4*>(qg + r * Ddim + 4 * j);
            *reinterpret_cast<uint2*>(QW + r * WST + 2 * j) =
                make_uint2(h2(f.x * scl, f.y * scl), h2(f.z * scl, f.w * scl));
        }
    }

    // ---- prologue: cp.async tile 0 -> wait -> convert into fp16 buf 0 ----
    {
        const float* kg = kbase + (size_t)(wn * 32) * Ddim;
        const float* vg = vbase + (size_t)(wn * 32) * Ddim;
        #pragma unroll
        for (int i = 0; i < 4; i++) {
            int c = tid_g + 256 * i;          // 0..1023
            int r = c >> 5, j = c & 31;
            cp16(kf + r * 128 + 4 * j, kg + r * Ddim + 4 * j);
            cp16(vf + r * 128 + 4 * j, vg + r * Ddim + 4 * j);
        }
        CP_COMMIT();
        CP_WAIT0();
        uint32_t* kd = smw + K16_OFF + (wn * 2 + 0) * 32 * WST;
        uint32_t* vd = smw + V16_OFF + (wn * 2 + 0) * 32 * WST;
        #pragma unroll
        for (int i = 0; i < 4; i++) {
            int c = tid_g + 256 * i;
            int r = c >> 5, j = c & 31;
            float4 f = *reinterpret_cast<const float4*>(kf + r * 128 + 4 * j);
            *reinterpret_cast<uint2*>(kd + r * WST + 2 * j) =
                make_uint2(h2(f.x, f.y), h2(f.z, f.w));
            float4 e = *reinterpret_cast<const float4*>(vf + r * 128 + 4 * j);
            *reinterpret_cast<uint2*>(vd + r * WST + 2 * j) =
                make_uint2(h2(e.x, e.y), h2(e.z, e.w));
        }
    }
    __syncthreads();

    float O[16][4];
    #pragma unroll
    for (int nd = 0; nd < 16; nd++)
        #pragma unroll
        for (int i = 0; i < 4; i++) O[nd][i] = 0.0f;

    // ---- main loop: 32 phases ----
    #pragma unroll 1
    for (int t = 0; t < NPH; t++) {
        const int buf = t & 1;
        const bool more = (t + 1 < NPH);

        bar_sync(1 + wn, 256);   // fp16[buf] ready; staging reads done

        // issue cp.async for tile t+1 (overlaps this phase's compute)
        if (more) {
            const float* kgn = kbase + (size_t)((t + 1) * PH_KV + wn * 32) * Ddim;
            const float* vgn = vbase + (size_t)((t + 1) * PH_KV + wn * 32) * Ddim;
            #pragma unroll
            for (int i = 0; i < 4; i++) {
                int c = tid_g + 256 * i;
                int r = c >> 5, j = c & 31;
                cp16(kf + r * 128 + 4 * j, kgn + r * Ddim + 4 * j);
                cp16(vf + r * 128 + 4 * j, vgn + r * Ddim + 4 * j);
            }
            CP_COMMIT();
        }

        const uint32_t kb_b = sb + 4 * (K16_OFF + (wn * 2 + buf) * 32 * WST
                                        + rl8 * WST + c4);
        const uint32_t vb_b = sb + 4 * (V16_OFF + (wn * 2 + buf) * 32 * WST
                                        + rl8 * WST + c4);

        // ---- GEMM1: S(m16 x kv32), 8 k16-steps, ldmatrix fragments ----
        float S[4][4];
        #pragma unroll
        for (int nb = 0; nb < 4; nb++)
            #pragma unroll
            for (int i = 0; i < 4; i++) S[nb][i] = 0.0f;

        #pragma unroll
        for (int kb = 0; kb < 8; kb++) {
            uint32_t A0[4], B0[4], B1[4];
            ldm4(qa0 + 32 * kb, A0);                      // m 0-15
            ldm4(kb_b + 32 * kb, B0);                     // kv 0-15
            ldm4(kb_b + 4 * 16 * WST + 32 * kb, B1);      // kv 16-31
            mma16(S[0], A0[0], A0[1], A0[2], A0[3], B0[0], B0[2]);
            mma16(S[1], A0[0], A0[1], A0[2], A0[3], B0[1], B0[3]);
            mma16(S[2], A0[0], A0[1], A0[2], A0[3], B1[0], B1[2]);
            mma16(S[3], A0[0], A0[1], A0[2], A0[3], B1[1], B1[3]);
        }

        // ---- P = relu(S)^2 (f16x2); GEMM2: O += P @ V (ldmatrix.trans) ----
        #pragma unroll
        for (int s2 = 0; s2 < 2; s2++) {
            uint32_t pA[4];
            pA[0] = hsq(h2(S[2 * s2][0],     S[2 * s2][1]));
            pA[1] = hsq(h2(S[2 * s2][2],     S[2 * s2][3]));
            pA[2] = hsq(h2(S[2 * s2 + 1][0], S[2 * s2 + 1][1]));
            pA[3] = hsq(h2(S[2 * s2 + 1][2], S[2 * s2 + 1][3]));
            const uint32_t va_b = vb_b + 4 * 16 * WST * s2;
            #pragma unroll
            for (int j = 0; j < 8; j++) {
                uint32_t Vr[4];
                ldm4t(va_b + 32 * j, Vr);    // b-frags for nd=2j, 2j+1
                mma16(O[2 * j],     pA[0], pA[1], pA[2], pA[3], Vr[0], Vr[1]);
                mma16(O[2 * j + 1], pA[0], pA[1], pA[2], pA[3], Vr[2], Vr[3]);
            }
        }

        // ---- wait + convert tile t+1 into spare fp16 buffer ----
        if (more) {
            CP_WAIT0();
            uint32_t* kd = smw + K16_OFF + (wn * 2 + (buf ^ 1)) * 32 * WST;
            uint32_t* vd = smw + V16_OFF + (wn * 2 + (buf ^ 1)) * 32 * WST;
            #pragma unroll
            for (int i = 0; i < 4; i++) {
                int c = tid_g + 256 * i;
                int r = c >> 5, j = c & 31;
                float4 f = *reinterpret_cast<const float4*>(kf + r * 128 + 4 * j);
                *reinterpret_cast<uint2*>(kd + r * WST + 2 * j) =
                    make_uint2(h2(f.x, f.y), h2(f.z, f.w));
                float4 e = *reinterpret_cast<const float4*>(vf + r * 128 + 4 * j);
                *reinterpret_cast<uint2*>(vd + r * WST + 2 * j) =
                    make_uint2(h2(e.x, e.y), h2(e.z, e.w));
            }
        }
    }

    // ---- reduce O across the two kv groups, write out ----
    __syncthreads();
    float* red = reinterpret_cast<float*>(smw);   // 128 x 132 floats
    if (wn == 1) {
        int r0 = wm * 16 + g;
        #pragma unroll
        for (int nd = 0; nd < 16; nd++) {
            *reinterpret_cast<float2*>(red + r0 * 132 + nd * 8 + 2 * t4) =
                make_float2(O[nd][0], O[nd][1]);
            *reinterpret_cast<float2*>(red + (r0 + 8) * 132 + nd * 8 + 2 * t4) =
                make_float2(O[nd][2], O[nd][3]);
        }
    }
    __syncthreads();
    if (wn == 0) {
        float* ob = out + ((size_t)bh * Sdim + q0) * Ddim;
        int r0 = wm * 16 + g;
        #pragma unroll
        for (int nd = 0; nd < 16; nd++) {
            float2 ra = *reinterpret_cast<const float2*>(red + r0 * 132 + nd * 8 + 2 * t4);
            float2 rb = *reinterpret_cast<const float2*>(red + (r0 + 8) * 132 + nd * 8 + 2 * t4);
            *reinterpret_cast<float2*>(ob + r0 * Ddim + nd * 8 + 2 * t4) =
                make_float2(O[nd][0] + ra.x, O[nd][1] + ra.y);
            *reinterpret_cast<float2*>(ob + (r0 + 8) * Ddim + nd * 8 + 2 * t4) =
                make_float2(O[nd][2] + rb.x, O[nd][3] + rb.y);
        }
    }
}

extern "C" void kernel_launch(void* const* d_in, const int* in_sizes, int n_in,
                              void* d_out, int out_size) {
    (void)in_sizes; (void)n_in; (void)out_size;
    const float* q = (const float*)d_in[0];
    const float* k = (const float*)d_in[1];
    const float* v = (const float*)d_in[2];
    const float* scale = (const float*)d_in[3];
    float* out = (float*)d_out;

    cudaFuncSetAttribute(attn_relu2_kernel,
                         cudaFuncAttributeMaxDynamicSharedMemorySize, SMEM_BYTES);

    dim3 grid(Bdim * Hdim * (Sdim / QT));   // 512 CTAs, bh-major
    attn_relu2_kernel<<<grid, NTHREADS, SMEM_BYTES>>>(q, k, v, scale, out);
}